// round 1
// baseline (speedup 1.0000x reference)
#include <cuda_runtime.h>
#include <math.h>
#include <float.h>

#define HIDDEN 5120
#define NH 40
#define HD 128
#define MAXL 2048
#define QL 8
#define CHUNK 256
#define NCHUNK (MAXL / CHUNK)
#define QK_SCALE 0.08838834764831845f  // 1/sqrt(128)

// ---------------- device scratch (no allocs allowed) ----------------
__device__ float g_q[NH * QL * HD];                    // [h][q][d], pre-scaled
__device__ float g_k[NH * QL * HD];                    // new K rows  [h][q][d]
__device__ float g_v[NH * QL * HD];                    // new V rows  [h][q][d]
__device__ float g_opart[NH * QL * NCHUNK * HD];       // [h][q][chunk][d]
__device__ float g_m[NH * QL * NCHUNK];                // chunk max
__device__ float g_l[NH * QL * NCHUNK];                // chunk expsum
__device__ float g_ctx[QL * HIDDEN];                   // attention output [q][h*128+d]

// ---------------------------------------------------------------
// GEMV with M=8: Y[q][r] = dot(X[q], W[r]) over C=HIDDEN columns.
// 8 rows per block, 8 queries register-tiled -> 64 accumulators.
// X staged through shared memory in 1024-col windows.
// mode 0: W_pack (3*HIDDEN rows) -> scatter into g_q/g_k/g_v
// mode 1: W_o (HIDDEN rows), X taken from g_ctx -> Y = d_out
// ---------------------------------------------------------------
__global__ void __launch_bounds__(256, 2) gemv8_kernel(
    const float* __restrict__ Xin, const float* __restrict__ W,
    float* __restrict__ Y, int mode)
{
    const int ROWS = 8;
    const int WIN = 1024;              // columns per smem window
    __shared__ float sx[QL * WIN];     // 32 KB
    __shared__ float sred[8][ROWS * QL];

    const float* __restrict__ X = (mode == 1) ? g_ctx : Xin;

    int tid = threadIdx.x;
    long r0 = (long)blockIdx.x * ROWS;

    float acc[ROWS][QL];
#pragma unroll
    for (int r = 0; r < ROWS; r++)
#pragma unroll
        for (int q = 0; q < QL; q++) acc[r][q] = 0.0f;

    for (int w0 = 0; w0 < HIDDEN; w0 += WIN) {
        __syncthreads();
        // cooperative load of X window: QL*WIN floats = 2048 float4
#pragma unroll
        for (int i = 0; i < (QL * WIN / 4) / 256; i++) {
            int idx = tid + i * 256;           // float4 index: q*256 + c
            int q = idx >> 8;
            int c = idx & 255;
            reinterpret_cast<float4*>(sx)[idx] =
                *reinterpret_cast<const float4*>(X + (long)q * HIDDEN + w0 + c * 4);
        }
        __syncthreads();

        int c4 = tid;                          // this thread's float4 column in window
        float4 wv[ROWS];
#pragma unroll
        for (int r = 0; r < ROWS; r++)
            wv[r] = *reinterpret_cast<const float4*>(
                W + (r0 + r) * (long)HIDDEN + w0 + c4 * 4);
#pragma unroll
        for (int q = 0; q < QL; q++) {
            float4 xv = reinterpret_cast<const float4*>(sx)[q * 256 + c4];
#pragma unroll
            for (int r = 0; r < ROWS; r++) {
                acc[r][q] = fmaf(wv[r].x, xv.x, acc[r][q]);
                acc[r][q] = fmaf(wv[r].y, xv.y, acc[r][q]);
                acc[r][q] = fmaf(wv[r].z, xv.z, acc[r][q]);
                acc[r][q] = fmaf(wv[r].w, xv.w, acc[r][q]);
            }
        }
    }

    // block reduction: warp shuffle then cross-warp via smem
    int lane = tid & 31, warp = tid >> 5;
#pragma unroll
    for (int r = 0; r < ROWS; r++) {
#pragma unroll
        for (int q = 0; q < QL; q++) {
            float v = acc[r][q];
            v += __shfl_down_sync(0xffffffffu, v, 16);
            v += __shfl_down_sync(0xffffffffu, v, 8);
            v += __shfl_down_sync(0xffffffffu, v, 4);
            v += __shfl_down_sync(0xffffffffu, v, 2);
            v += __shfl_down_sync(0xffffffffu, v, 1);
            if (lane == 0) sred[warp][r * QL + q] = v;
        }
    }
    __syncthreads();
    if (tid < ROWS * QL) {
        float v = 0.0f;
#pragma unroll
        for (int w = 0; w < 8; w++) v += sred[w][tid];
        long r = r0 + tid / QL;
        int q = tid % QL;
        if (mode == 0) {
            int sect = (int)(r / HIDDEN);      // 0=q, 1=k, 2=v
            int f = (int)(r % HIDDEN);
            int h = f / HD, d = f % HD;
            int o = (h * QL + q) * HD + d;
            if (sect == 0)      g_q[o] = v * QK_SCALE;
            else if (sect == 1) g_k[o] = v;
            else                g_v[o] = v;
        } else {
            Y[(long)q * HIDDEN + r] = v;
        }
    }
}

// ---------------------------------------------------------------
// Split-KV attention: block = (chunk of 256 keys, head).
// Emulates the KV-cache scatter by selecting new K/V rows for keys
// matching input_pos. Writes unnormalized partial O + (m, l).
// ---------------------------------------------------------------
__global__ void __launch_bounds__(256) attn_kernel(
    const float* __restrict__ kc, const float* __restrict__ vc,
    const float* __restrict__ mask, const int* __restrict__ ipos)
{
    int chunk = blockIdx.x;
    int h = blockIdx.y;
    int tid = threadIdx.x;

    __shared__ float qs[QL][HD];        // 4 KB
    __shared__ float sc[QL][CHUNK];     // 8 KB, scores then probs
    __shared__ float red[QL][HD];       // 4 KB
    __shared__ int pos[QL];
    __shared__ int sel[CHUNK];

    // read input_pos; tolerate int64 layout (high word of first elem == 0)
    if (tid == 0) {
        bool is64 = (ipos[1] == 0 && ipos[0] != 0);
#pragma unroll
        for (int j = 0; j < QL; j++) pos[j] = is64 ? ipos[2 * j] : ipos[j];
    }
    for (int i = tid; i < QL * HD; i += 256) qs[0][i] = g_q[h * QL * HD + i];
    __syncthreads();

    int key = chunk * CHUNK + tid;      // one key per thread
    int s = -1;
#pragma unroll
    for (int j = 0; j < QL; j++) if (pos[j] == key) s = j;
    sel[tid] = s;

    const float* kp = (s >= 0) ? &g_k[(h * QL + s) * HD]
                               : &kc[((size_t)h * MAXL + key) * HD];
    float a[QL];
#pragma unroll
    for (int q = 0; q < QL; q++) a[q] = 0.0f;
#pragma unroll 4
    for (int c = 0; c < HD; c += 4) {
        float4 kv = *reinterpret_cast<const float4*>(kp + c);
#pragma unroll
        for (int q = 0; q < QL; q++) {
            float4 qv = *reinterpret_cast<const float4*>(&qs[q][c]);
            a[q] = fmaf(kv.x, qv.x, a[q]);
            a[q] = fmaf(kv.y, qv.y, a[q]);
            a[q] = fmaf(kv.z, qv.z, a[q]);
            a[q] = fmaf(kv.w, qv.w, a[q]);
        }
    }
    // q already carries 1/sqrt(d); add mask[h][pos[q]][key]
#pragma unroll
    for (int q = 0; q < QL; q++) {
        float m = mask[((size_t)h * MAXL + pos[q]) * MAXL + key];
        sc[q][tid] = fmaxf(a[q] + m, -FLT_MAX);
    }
    __syncthreads();

    // per-(q=warp) softmax stats over the chunk
    int warp = tid >> 5, lane = tid & 31;
    {
        float m = -FLT_MAX;
#pragma unroll
        for (int i = 0; i < CHUNK / 32; i++) m = fmaxf(m, sc[warp][lane + i * 32]);
#pragma unroll
        for (int o = 16; o > 0; o >>= 1) m = fmaxf(m, __shfl_xor_sync(0xffffffffu, m, o));
        float l = 0.0f;
#pragma unroll
        for (int i = 0; i < CHUNK / 32; i++) {
            float p = __expf(sc[warp][lane + i * 32] - m);
            sc[warp][lane + i * 32] = p;
            l += p;
        }
#pragma unroll
        for (int o = 16; o > 0; o >>= 1) l += __shfl_xor_sync(0xffffffffu, l, o);
        if (lane == 0) {
            g_m[(h * QL + warp) * NCHUNK + chunk] = m;
            g_l[(h * QL + warp) * NCHUNK + chunk] = l;
        }
    }
    __syncthreads();

    // partial O = P^T V; thread owns dim d, two key-halves in parallel
    int d = tid & 127, half = tid >> 7;
    float acc[QL];
#pragma unroll
    for (int q = 0; q < QL; q++) acc[q] = 0.0f;
    int kbeg = half * (CHUNK / 2);
#pragma unroll 4
    for (int k = kbeg; k < kbeg + CHUNK / 2; k++) {
        int kk = chunk * CHUNK + k;
        int sv = sel[k];
        float vv = (sv >= 0) ? g_v[(h * QL + sv) * HD + d]
                             : vc[((size_t)h * MAXL + kk) * HD + d];
#pragma unroll
        for (int q = 0; q < QL; q++) acc[q] = fmaf(sc[q][k], vv, acc[q]);
    }
    if (half == 1) {
#pragma unroll
        for (int q = 0; q < QL; q++) red[q][d] = acc[q];
    }
    __syncthreads();
    if (half == 0) {
#pragma unroll
        for (int q = 0; q < QL; q++) {
            float o = acc[q] + red[q][d];
            g_opart[((h * QL + q) * NCHUNK + chunk) * HD + d] = o;
        }
    }
}

// ---------------------------------------------------------------
// Combine split-KV partials (log-sum-exp merge) -> context [q][h*128+d]
// ---------------------------------------------------------------
__global__ void __launch_bounds__(HD) combine_kernel()
{
    int hq = blockIdx.x;                // h*QL + q
    int d = threadIdx.x;
    float mv[NCHUNK];
    float M = -FLT_MAX;
#pragma unroll
    for (int c = 0; c < NCHUNK; c++) {
        mv[c] = g_m[hq * NCHUNK + c];
        M = fmaxf(M, mv[c]);
    }
    float wf[NCHUNK];
    float denom = 0.0f;
#pragma unroll
    for (int c = 0; c < NCHUNK; c++) {
        wf[c] = __expf(mv[c] - M);
        denom += g_l[hq * NCHUNK + c] * wf[c];
    }
    float o = 0.0f;
#pragma unroll
    for (int c = 0; c < NCHUNK; c++)
        o += wf[c] * g_opart[(hq * NCHUNK + c) * HD + d];
    o /= denom;
    int h = hq / QL, q = hq % QL;
    g_ctx[q * HIDDEN + h * HD + d] = o;
}

// ---------------------------------------------------------------
extern "C" void kernel_launch(void* const* d_in, const int* in_sizes, int n_in,
                              void* d_out, int out_size)
{
    const int*   ipos  = (const int*)  d_in[0];
    const float* hs    = (const float*)d_in[1];
    const float* mask  = (const float*)d_in[2];
    const float* wpack = (const float*)d_in[3];
    const float* wo    = (const float*)d_in[4];
    const float* kc    = (const float*)d_in[5];
    const float* vc    = (const float*)d_in[6];
    float* out = (float*)d_out;

    // 1) fused QKV projection -> g_q/g_k/g_v
    gemv8_kernel<<<(3 * HIDDEN) / 8, 256>>>(hs, wpack, nullptr, 0);

    // 2) split-KV attention partials
    dim3 ag(NCHUNK, NH);
    attn_kernel<<<ag, 256>>>(kc, vc, mask, ipos);

    // 3) merge partials -> context
    combine_kernel<<<NH * QL, HD>>>();

    // 4) output projection -> d_out
    gemv8_kernel<<<HIDDEN / 8, 256>>>(nullptr, wo, out, 1);
}

// round 2
// speedup vs baseline: 1.1190x; 1.1190x over previous
#include <cuda_runtime.h>
#include <math.h>
#include <float.h>

#define HIDDEN 5120
#define NH 40
#define HD 128
#define MAXL 2048
#define QL 8
#define CHUNK 256
#define NCHUNK (MAXL / CHUNK)
#define QK_SCALE 0.08838834764831845f  // 1/sqrt(128)
#define C4 (HIDDEN / 4)                // 1280 float4 per row

// ---------------- device scratch (no allocs allowed) ----------------
__device__ float g_q[NH * QL * HD];                    // [h][q][d], pre-scaled
__device__ float g_k[NH * QL * HD];                    // new K rows  [h][q][d]
__device__ float g_v[NH * QL * HD];                    // new V rows  [h][q][d]
__device__ float g_opart[NH * QL * NCHUNK * HD];       // [h][q][chunk][d]
__device__ float g_m[NH * QL * NCHUNK];                // chunk max
__device__ float g_l[NH * QL * NCHUNK];                // chunk expsum
__device__ float g_ctx[QL * HIDDEN];                   // attention output [q][h*128+d]

// ---------------------------------------------------------------
// GEMV, M=8: Y[q][r] = dot(X[q], W[r]). 8 rows/block, 8 q register tile.
// No smem staging: X read straight from gmem (hits L2; each element read
// once per block). Main loop is barrier-free with MLP=16 per thread.
// mode 0: W_pack -> scatter into g_q/g_k/g_v.  mode 1: W_o, X=g_ctx -> Y.
// ---------------------------------------------------------------
__global__ void __launch_bounds__(256, 2) gemv8_kernel(
    const float* __restrict__ Xin, const float* __restrict__ W,
    float* __restrict__ Y, int mode)
{
    __shared__ float sred[8][64];      // 8 warps x (8 rows * 8 q)

    const float4* __restrict__ X4 =
        reinterpret_cast<const float4*>((mode == 1) ? g_ctx : Xin);
    const float4* __restrict__ W4 = reinterpret_cast<const float4*>(W);

    int tid = threadIdx.x;
    long r0 = (long)blockIdx.x * 8;
    const float4* __restrict__ Wp = W4 + (size_t)r0 * C4;

    float acc[8][8];
#pragma unroll
    for (int r = 0; r < 8; r++)
#pragma unroll
        for (int q = 0; q < 8; q++) acc[r][q] = 0.0f;

#pragma unroll 1
    for (int c4 = tid; c4 < C4; c4 += 256) {
        float4 wv[8];
#pragma unroll
        for (int r = 0; r < 8; r++)
            wv[r] = __ldg(Wp + (size_t)r * C4 + c4);
#pragma unroll
        for (int q = 0; q < 8; q++) {
            float4 xv = __ldg(X4 + q * C4 + c4);
#pragma unroll
            for (int r = 0; r < 8; r++) {
                acc[r][q] = fmaf(wv[r].x, xv.x, acc[r][q]);
                acc[r][q] = fmaf(wv[r].y, xv.y, acc[r][q]);
                acc[r][q] = fmaf(wv[r].z, xv.z, acc[r][q]);
                acc[r][q] = fmaf(wv[r].w, xv.w, acc[r][q]);
            }
        }
    }

    // block reduction: warp shuffle then cross-warp via smem
    int lane = tid & 31, warp = tid >> 5;
#pragma unroll
    for (int r = 0; r < 8; r++) {
#pragma unroll
        for (int q = 0; q < 8; q++) {
            float v = acc[r][q];
            v += __shfl_down_sync(0xffffffffu, v, 16);
            v += __shfl_down_sync(0xffffffffu, v, 8);
            v += __shfl_down_sync(0xffffffffu, v, 4);
            v += __shfl_down_sync(0xffffffffu, v, 2);
            v += __shfl_down_sync(0xffffffffu, v, 1);
            if (lane == 0) sred[warp][r * 8 + q] = v;
        }
    }
    __syncthreads();
    if (tid < 64) {
        float v = 0.0f;
#pragma unroll
        for (int w = 0; w < 8; w++) v += sred[w][tid];
        long r = r0 + tid / 8;
        int q = tid % 8;
        if (mode == 0) {
            int sect = (int)(r / HIDDEN);      // 0=q, 1=k, 2=v
            int f = (int)(r % HIDDEN);
            int h = f / HD, d = f % HD;
            int o = (h * QL + q) * HD + d;
            if (sect == 0)      g_q[o] = v * QK_SCALE;
            else if (sect == 1) g_k[o] = v;
            else                g_v[o] = v;
        } else {
            Y[(long)q * HIDDEN + r] = v;
        }
    }
}

// ---------------------------------------------------------------
// Split-KV attention: block = (chunk of 256 keys, head).
// Scatter emulated by per-key select vs input_pos. V phase: warp owns a
// key stride, lane owns a d-float4, 4-deep prefetch for MLP.
// ---------------------------------------------------------------
__global__ void __launch_bounds__(256) attn_kernel(
    const float* __restrict__ kc, const float* __restrict__ vc,
    const float* __restrict__ mask, const int* __restrict__ ipos)
{
    int chunk = blockIdx.x;
    int h = blockIdx.y;
    int tid = threadIdx.x;
    int warp = tid >> 5, lane = tid & 31;

    __shared__ float qs[QL][HD];        // 4 KB
    __shared__ float sc[QL][CHUNK];     // 8 KB, scores then probs
    __shared__ float4 red[8][QL][32];   // 32 KB: per-warp partial O
    __shared__ int pos[QL];
    __shared__ int sel[CHUNK];

    if (tid == 0) {
        bool is64 = (ipos[1] == 0);     // int64 little-endian high word
#pragma unroll
        for (int j = 0; j < QL; j++) pos[j] = is64 ? ipos[2 * j] : ipos[j];
    }
    for (int i = tid; i < QL * HD; i += 256) qs[0][i] = g_q[h * QL * HD + i];
    __syncthreads();

    // ---- scores: one key per thread ----
    int key = chunk * CHUNK + tid;
    int s = -1;
#pragma unroll
    for (int j = 0; j < QL; j++) if (pos[j] == key) s = j;
    sel[tid] = s;

    const float4* kp = reinterpret_cast<const float4*>(
        (s >= 0) ? &g_k[(h * QL + s) * HD]
                 : &kc[((size_t)h * MAXL + key) * HD]);
    float a[QL];
#pragma unroll
    for (int q = 0; q < QL; q++) a[q] = 0.0f;
#pragma unroll
    for (int c = 0; c < HD / 4; c += 8) {
        float4 kv[8];
#pragma unroll
        for (int u = 0; u < 8; u++) kv[u] = __ldg(kp + c + u);
#pragma unroll
        for (int u = 0; u < 8; u++) {
#pragma unroll
            for (int q = 0; q < QL; q++) {
                float4 qv = *reinterpret_cast<const float4*>(&qs[q][(c + u) * 4]);
                a[q] = fmaf(kv[u].x, qv.x, a[q]);
                a[q] = fmaf(kv[u].y, qv.y, a[q]);
                a[q] = fmaf(kv[u].z, qv.z, a[q]);
                a[q] = fmaf(kv[u].w, qv.w, a[q]);
            }
        }
    }
#pragma unroll
    for (int q = 0; q < QL; q++) {
        float m = __ldg(&mask[((size_t)h * MAXL + pos[q]) * MAXL + key]);
        sc[q][tid] = fmaxf(a[q] + m, -FLT_MAX);
    }
    __syncthreads();

    // ---- softmax stats: warp q handles query q (warps 0..7 <-> q 0..7) ----
    {
        float m = -FLT_MAX;
#pragma unroll
        for (int i = 0; i < CHUNK / 32; i++) m = fmaxf(m, sc[warp][lane + i * 32]);
#pragma unroll
        for (int o = 16; o > 0; o >>= 1) m = fmaxf(m, __shfl_xor_sync(0xffffffffu, m, o));
        float l = 0.0f;
#pragma unroll
        for (int i = 0; i < CHUNK / 32; i++) {
            float p = __expf(sc[warp][lane + i * 32] - m);
            sc[warp][lane + i * 32] = p;
            l += p;
        }
#pragma unroll
        for (int o = 16; o > 0; o >>= 1) l += __shfl_xor_sync(0xffffffffu, l, o);
        if (lane == 0) {
            g_m[(h * QL + warp) * NCHUNK + chunk] = m;
            g_l[(h * QL + warp) * NCHUNK + chunk] = l;
        }
    }
    __syncthreads();

    // ---- partial O = P^T V. warp w: keys w, w+8, ...; lane: d-float4 ----
    float4 acc[QL];
#pragma unroll
    for (int q = 0; q < QL; q++) acc[q] = make_float4(0.f, 0.f, 0.f, 0.f);

#pragma unroll
    for (int j = 0; j < 32; j += 4) {
        float4 vv[4];
#pragma unroll
        for (int u = 0; u < 4; u++) {
            int k = warp + 8 * (j + u);
            int sv = sel[k];
            int kk = chunk * CHUNK + k;
            const float4* vp = reinterpret_cast<const float4*>(
                (sv >= 0) ? &g_v[(h * QL + sv) * HD]
                          : &vc[((size_t)h * MAXL + kk) * HD]);
            vv[u] = __ldg(vp + lane);
        }
#pragma unroll
        for (int u = 0; u < 4; u++) {
            int k = warp + 8 * (j + u);
#pragma unroll
            for (int q = 0; q < QL; q++) {
                float p = sc[q][k];
                acc[q].x = fmaf(p, vv[u].x, acc[q].x);
                acc[q].y = fmaf(p, vv[u].y, acc[q].y);
                acc[q].z = fmaf(p, vv[u].z, acc[q].z);
                acc[q].w = fmaf(p, vv[u].w, acc[q].w);
            }
        }
    }
#pragma unroll
    for (int q = 0; q < QL; q++) red[warp][q][lane] = acc[q];
    __syncthreads();

    // reduce 8 warps: thread t handles (q, d4) = (t/32, t%32)
    {
        int q = tid >> 5, d4 = tid & 31;
        float4 o = red[0][q][d4];
#pragma unroll
        for (int w = 1; w < 8; w++) {
            float4 v = red[w][q][d4];
            o.x += v.x; o.y += v.y; o.z += v.z; o.w += v.w;
        }
        reinterpret_cast<float4*>(
            &g_opart[((h * QL + q) * NCHUNK + chunk) * HD])[d4] = o;
    }
}

// ---------------------------------------------------------------
// Combine split-KV partials (log-sum-exp merge) -> context [q][h*128+d]
// ---------------------------------------------------------------
__global__ void __launch_bounds__(HD) combine_kernel()
{
    int hq = blockIdx.x;                // h*QL + q
    int d = threadIdx.x;
    float mv[NCHUNK];
    float M = -FLT_MAX;
#pragma unroll
    for (int c = 0; c < NCHUNK; c++) {
        mv[c] = g_m[hq * NCHUNK + c];
        M = fmaxf(M, mv[c]);
    }
    float wf[NCHUNK];
    float denom = 0.0f;
#pragma unroll
    for (int c = 0; c < NCHUNK; c++) {
        wf[c] = __expf(mv[c] - M);
        denom += g_l[hq * NCHUNK + c] * wf[c];
    }
    float o = 0.0f;
#pragma unroll
    for (int c = 0; c < NCHUNK; c++)
        o += wf[c] * g_opart[(hq * NCHUNK + c) * HD + d];
    o /= denom;
    int h = hq / QL, q = hq % QL;
    g_ctx[q * HIDDEN + h * HD + d] = o;
}

// ---------------------------------------------------------------
extern "C" void kernel_launch(void* const* d_in, const int* in_sizes, int n_in,
                              void* d_out, int out_size)
{
    const int*   ipos  = (const int*)  d_in[0];
    const float* hs    = (const float*)d_in[1];
    const float* mask  = (const float*)d_in[2];
    const float* wpack = (const float*)d_in[3];
    const float* wo    = (const float*)d_in[4];
    const float* kc    = (const float*)d_in[5];
    const float* vc    = (const float*)d_in[6];
    float* out = (float*)d_out;

    // 1) fused QKV projection -> g_q/g_k/g_v
    gemv8_kernel<<<(3 * HIDDEN) / 8, 256>>>(hs, wpack, nullptr, 0);

    // 2) split-KV attention partials
    dim3 ag(NCHUNK, NH);
    attn_kernel<<<ag, 256>>>(kc, vc, mask, ipos);

    // 3) merge partials -> context
    combine_kernel<<<NH * QL, HD>>>();

    // 4) output projection -> d_out
    gemv8_kernel<<<HIDDEN / 8, 256>>>(nullptr, wo, out, 1);
}